// round 1
// baseline (speedup 1.0000x reference)
#include <cuda_runtime.h>

// Problem constants (fixed by setup_inputs)
#define H      512
#define NC     64
#define NS     5
#define NQ     15
#define NROWS  1280   // 64 * (5+15)
#define NQTOT  960    // 64 * 15

// Scratch for att = x @ W^T + b  (1280 x 512 fp32)
__device__ float g_att[NROWS * H];

// tanh via EX2+RCP: abs err ~1e-6, 2 MUFU ops.
// Handles all magnitudes: expf(2x)->inf => 1, ->0 => -1.
__device__ __forceinline__ float tanh_fast(float x) {
    float e = __expf(2.0f * x);
    return 1.0f - __fdividef(2.0f, 1.0f + e);
}

// ---------------------------------------------------------------------------
// Kernel 1: g_att[r][n] = sum_k X[r][k] * W[n][k] + b[n]
// 64x64 tile, 256 threads, 4x4 micro-tile per thread, BK=16, smem transposed.
// ---------------------------------------------------------------------------
__global__ __launch_bounds__(256) void gemm_xwt(const float* __restrict__ X,
                                                const float* __restrict__ W,
                                                const float* __restrict__ bias) {
    __shared__ float As[16][68];   // [k][m], pad 68 keeps float4 16B alignment
    __shared__ float Bs[16][68];   // [k][n]
    const int t  = threadIdx.x;
    const int tx = t & 15;         // 16 x 16 thread grid
    const int ty = t >> 4;
    const int m0 = blockIdx.y * 64;
    const int n0 = blockIdx.x * 64;
    const int lr = t >> 2;         // row to load (0..63)
    const int lk = (t & 3) << 2;   // k offset (0,4,8,12)

    float acc[4][4] = {};

    for (int kk = 0; kk < H; kk += 16) {
        float4 av = *(const float4*)&X[(m0 + lr) * H + kk + lk];
        float4 bv = *(const float4*)&W[(n0 + lr) * H + kk + lk];
        As[lk + 0][lr] = av.x; As[lk + 1][lr] = av.y;
        As[lk + 2][lr] = av.z; As[lk + 3][lr] = av.w;
        Bs[lk + 0][lr] = bv.x; Bs[lk + 1][lr] = bv.y;
        Bs[lk + 2][lr] = bv.z; Bs[lk + 3][lr] = bv.w;
        __syncthreads();
        #pragma unroll
        for (int k = 0; k < 16; k++) {
            float4 a4 = *(const float4*)&As[k][ty << 2];
            float4 b4 = *(const float4*)&Bs[k][tx << 2];
            float ar[4] = {a4.x, a4.y, a4.z, a4.w};
            float br[4] = {b4.x, b4.y, b4.z, b4.w};
            #pragma unroll
            for (int i = 0; i < 4; i++)
                #pragma unroll
                for (int j = 0; j < 4; j++)
                    acc[i][j] = fmaf(ar[i], br[j], acc[i][j]);
        }
        __syncthreads();
    }

    #pragma unroll
    for (int i = 0; i < 4; i++) {
        const int r = m0 + (ty << 2) + i;
        #pragma unroll
        for (int j = 0; j < 4; j++) {
            const int n = n0 + (tx << 2) + j;
            g_att[r * H + n] = acc[i][j] + bias[n];
        }
    }
}

// ---------------------------------------------------------------------------
// Kernel 2: fused scores -> softmax -> proto -> dists.
// grid = (64 support-classes, 8 query-class groups), 256 threads (8 warps).
// Block stages s_att[c] (5x512) and support[c] (5x512) in SMEM.
// Warp w handles query-class qc = blockIdx.y*8 + w : its 15 queries vs class c.
// Per query: lanes stride H as float4, 5 score accumulators, warp-reduce,
// softmax over 5 in registers, then proto/dist pass and warp-reduce.
// ---------------------------------------------------------------------------
__global__ __launch_bounds__(256) void proto_attn(const float* __restrict__ X,
                                                  float* __restrict__ out) {
    const int c    = blockIdx.x;
    const int qb   = blockIdx.y;
    const int t    = threadIdx.x;
    const int warp = t >> 5;
    const int lane = t & 31;

    __shared__ float4 sA[NS * 128];   // s_att rows of class c (tanh operand)
    __shared__ float4 sS[NS * 128];   // raw support rows of class c (proto)

    const float4* attv = (const float4*)g_att;
    const float4* xv   = (const float4*)X;

    for (int i = t; i < NS * 128; i += 256) {
        const int s   = i >> 7;
        const int off = i & 127;
        const int row = c * 20 + s;          // support row s of class c
        sA[i] = attv[row * 128 + off];
        sS[i] = xv[row * 128 + off];
    }
    __syncthreads();

    const int qc = qb * 8 + warp;            // query's own class (0..63)

    for (int j = 0; j < NQ; j++) {
        const int row = qc * 20 + NS + j;    // query row in x / g_att
        const float4* qa = attv + row * 128;

        float acc[NS] = {0.f, 0.f, 0.f, 0.f, 0.f};
        #pragma unroll
        for (int i = 0; i < 4; i++) {
            const float4 a = qa[lane + i * 32];
            #pragma unroll
            for (int s = 0; s < NS; s++) {
                const float4 b = sA[s * 128 + lane + i * 32];
                acc[s] += tanh_fast(a.x * b.x);
                acc[s] += tanh_fast(a.y * b.y);
                acc[s] += tanh_fast(a.z * b.z);
                acc[s] += tanh_fast(a.w * b.w);
            }
        }
        #pragma unroll
        for (int s = 0; s < NS; s++) {
            #pragma unroll
            for (int o = 16; o > 0; o >>= 1)
                acc[s] += __shfl_xor_sync(0xffffffffu, acc[s], o);
        }

        // softmax over the 5 support scores (all lanes hold full sums)
        float m = acc[0];
        #pragma unroll
        for (int s = 1; s < NS; s++) m = fmaxf(m, acc[s]);
        float w[NS];
        float sum = 0.f;
        #pragma unroll
        for (int s = 0; s < NS; s++) { w[s] = __expf(acc[s] - m); sum += w[s]; }
        const float inv = __fdividef(1.0f, sum);
        #pragma unroll
        for (int s = 0; s < NS; s++) w[s] *= inv;

        // proto = sum_s w[s]*support[c,s,:]; dist = ||proto - query||^2
        const float4* qx = xv + row * 128;
        float d = 0.f;
        #pragma unroll
        for (int i = 0; i < 4; i++) {
            const float4 qv = qx[lane + i * 32];
            float px = 0.f, py = 0.f, pz = 0.f, pw = 0.f;
            #pragma unroll
            for (int s = 0; s < NS; s++) {
                const float4 sv = sS[s * 128 + lane + i * 32];
                px = fmaf(w[s], sv.x, px);
                py = fmaf(w[s], sv.y, py);
                pz = fmaf(w[s], sv.z, pz);
                pw = fmaf(w[s], sv.w, pw);
            }
            const float dx = px - qv.x, dy = py - qv.y;
            const float dz = pz - qv.z, dw = pw - qv.w;
            d += dx * dx + dy * dy + dz * dz + dw * dw;
        }
        #pragma unroll
        for (int o = 16; o > 0; o >>= 1)
            d += __shfl_xor_sync(0xffffffffu, d, o);

        if (lane == 0) {
            const int q = qc * NQ + j;       // 0..959
            out[q * NC + c] = d;
        }
    }
}

extern "C" void kernel_launch(void* const* d_in, const int* in_sizes, int n_in,
                              void* d_out, int out_size) {
    const float* x = (const float*)d_in[0];   // (1280, 512) f32
    const float* W = (const float*)d_in[1];   // (512, 512)  f32
    const float* b = (const float*)d_in[2];   // (512,)      f32
    float* out = (float*)d_out;               // (960, 64)   f32

    gemm_xwt<<<dim3(H / 64, NROWS / 64), 256>>>(x, W, b);
    proto_attn<<<dim3(NC, 8), 256>>>(x, out);
}

// round 2
// speedup vs baseline: 1.3253x; 1.3253x over previous
#include <cuda_runtime.h>

#define H      512
#define NC     64
#define NS     5
#define NQ     15
#define NROWS  1280
#define NQTOT  960

__device__ float g_att[NROWS * H];

// Hardware tanh: 1 MUFU op (vs 2 for EX2+RCP). abs err ~5e-4 per element;
// verified against the 1e-3 output threshold via measured rel_err.
__device__ __forceinline__ float tanh_approx(float x) {
    float y;
    asm("tanh.approx.f32 %0, %1;" : "=f"(y) : "f"(x));
    return y;
}

// ---------------------------------------------------------------------------
// Kernel 1: g_att[r][n] = sum_k X[r][k] * W[n][k] + b[n]
// 32x64 tile (320 blocks -> smooth wave balance on 148 SMs), 256 threads,
// 2x4 micro-tile per thread, BK=16.
// ---------------------------------------------------------------------------
__global__ __launch_bounds__(256) void gemm_xwt(const float* __restrict__ X,
                                                const float* __restrict__ W,
                                                const float* __restrict__ bias) {
    __shared__ float As[16][36];   // [k][m] for 32 m-rows (pad to 36)
    __shared__ float Bs[16][68];   // [k][n] for 64 n-rows
    const int t  = threadIdx.x;
    const int tx = t & 15;         // n tile: 16 threads x 4
    const int ty = t >> 4;         // m tile: 16 threads x 2
    const int m0 = blockIdx.y * 32;
    const int n0 = blockIdx.x * 64;

    const int lr = t >> 2;         // 0..63
    const int lk = (t & 3) << 2;   // 0,4,8,12

    float acc[2][4] = {};

    for (int kk = 0; kk < H; kk += 16) {
        if (t < 128) {             // A: 32 rows x 16 k
            float4 av = *(const float4*)&X[(m0 + lr) * H + kk + lk];
            As[lk + 0][lr] = av.x; As[lk + 1][lr] = av.y;
            As[lk + 2][lr] = av.z; As[lk + 3][lr] = av.w;
        }
        {                          // B: 64 rows x 16 k
            float4 bv = *(const float4*)&W[(n0 + lr) * H + kk + lk];
            Bs[lk + 0][lr] = bv.x; Bs[lk + 1][lr] = bv.y;
            Bs[lk + 2][lr] = bv.z; Bs[lk + 3][lr] = bv.w;
        }
        __syncthreads();
        #pragma unroll
        for (int k = 0; k < 16; k++) {
            const float a0 = As[k][(ty << 1) + 0];
            const float a1 = As[k][(ty << 1) + 1];
            float4 b4 = *(const float4*)&Bs[k][tx << 2];
            float br[4] = {b4.x, b4.y, b4.z, b4.w};
            #pragma unroll
            for (int j = 0; j < 4; j++) {
                acc[0][j] = fmaf(a0, br[j], acc[0][j]);
                acc[1][j] = fmaf(a1, br[j], acc[1][j]);
            }
        }
        __syncthreads();
    }

    #pragma unroll
    for (int i = 0; i < 2; i++) {
        const int r = m0 + (ty << 1) + i;
        #pragma unroll
        for (int j = 0; j < 4; j++) {
            const int n = n0 + (tx << 2) + j;
            g_att[r * H + n] = acc[i][j] + bias[n];
        }
    }
}

// ---------------------------------------------------------------------------
// Kernel 2: fused scores -> softmax -> proto -> dists.
// grid = (64 support-classes, 8 query-class groups), 256 threads (8 warps).
// ---------------------------------------------------------------------------
__global__ __launch_bounds__(256) void proto_attn(const float* __restrict__ X,
                                                  float* __restrict__ out) {
    const int c    = blockIdx.x;
    const int qb   = blockIdx.y;
    const int t    = threadIdx.x;
    const int warp = t >> 5;
    const int lane = t & 31;

    __shared__ float4 sA[NS * 128];   // s_att rows of class c
    __shared__ float4 sS[NS * 128];   // raw support rows of class c

    const float4* attv = (const float4*)g_att;
    const float4* xv   = (const float4*)X;

    for (int i = t; i < NS * 128; i += 256) {
        const int s   = i >> 7;
        const int off = i & 127;
        const int row = c * 20 + s;
        sA[i] = attv[row * 128 + off];
        sS[i] = xv[row * 128 + off];
    }
    __syncthreads();

    const int qc = qb * 8 + warp;

    for (int j = 0; j < NQ; j++) {
        const int row = qc * 20 + NS + j;
        const float4* qa = attv + row * 128;

        float acc[NS] = {0.f, 0.f, 0.f, 0.f, 0.f};
        #pragma unroll
        for (int i = 0; i < 4; i++) {
            const float4 a = qa[lane + i * 32];
            #pragma unroll
            for (int s = 0; s < NS; s++) {
                const float4 b = sA[s * 128 + lane + i * 32];
                acc[s] += tanh_approx(a.x * b.x);
                acc[s] += tanh_approx(a.y * b.y);
                acc[s] += tanh_approx(a.z * b.z);
                acc[s] += tanh_approx(a.w * b.w);
            }
        }
        #pragma unroll
        for (int s = 0; s < NS; s++) {
            #pragma unroll
            for (int o = 16; o > 0; o >>= 1)
                acc[s] += __shfl_xor_sync(0xffffffffu, acc[s], o);
        }

        float m = acc[0];
        #pragma unroll
        for (int s = 1; s < NS; s++) m = fmaxf(m, acc[s]);
        float w[NS];
        float sum = 0.f;
        #pragma unroll
        for (int s = 0; s < NS; s++) { w[s] = __expf(acc[s] - m); sum += w[s]; }
        const float inv = __fdividef(1.0f, sum);
        #pragma unroll
        for (int s = 0; s < NS; s++) w[s] *= inv;

        const float4* qx = xv + row * 128;
        float d = 0.f;
        #pragma unroll
        for (int i = 0; i < 4; i++) {
            const float4 qv = qx[lane + i * 32];
            float px = 0.f, py = 0.f, pz = 0.f, pw = 0.f;
            #pragma unroll
            for (int s = 0; s < NS; s++) {
                const float4 sv = sS[s * 128 + lane + i * 32];
                px = fmaf(w[s], sv.x, px);
                py = fmaf(w[s], sv.y, py);
                pz = fmaf(w[s], sv.z, pz);
                pw = fmaf(w[s], sv.w, pw);
            }
            const float dx = px - qv.x, dy = py - qv.y;
            const float dz = pz - qv.z, dw = pw - qv.w;
            d += dx * dx + dy * dy + dz * dz + dw * dw;
        }
        #pragma unroll
        for (int o = 16; o > 0; o >>= 1)
            d += __shfl_xor_sync(0xffffffffu, d, o);

        if (lane == 0) {
            const int q = qc * NQ + j;
            out[q * NC + c] = d;
        }
    }
}

extern "C" void kernel_launch(void* const* d_in, const int* in_sizes, int n_in,
                              void* d_out, int out_size) {
    const float* x = (const float*)d_in[0];
    const float* W = (const float*)d_in[1];
    const float* b = (const float*)d_in[2];
    float* out = (float*)d_out;

    gemm_xwt<<<dim3(H / 64, NROWS / 32), 256>>>(x, W, b);
    proto_attn<<<dim3(NC, 8), 256>>>(x, out);
}